// round 1
// baseline (speedup 1.0000x reference)
#include <cuda_runtime.h>
#include <math.h>

#define HID 512
#define QD 32
#define OFFN 496

// ---------------- scratch (device globals; no allocation allowed) ----------
__device__ float d_h1[HID], d_g1[HID], d_h2[HID], d_g2[HID], d_h3[HID];
__device__ float d_A1[HID * QD];            // diag(s1) @ W1
__device__ float d_M1[HID * QD];            // diag(s2) W2 diag(s1) W1
__device__ float d_M2[HID * QD];            // diag(s3) W3 M1
__device__ float d_M3[(QD + OFFN) * QD];    // dh4 @ M2  == dl_dq [528,32]
__device__ float d_ldiag[QD], d_loff[OFFN], d_gvec[QD];

__device__ __forceinline__ float sigm(float x) { return 1.f / (1.f + expf(-x)); }

// warp computes dot(W[0:512], x[0:512]); result valid in all lanes
__device__ __forceinline__ float warp_dot512(const float* __restrict__ W,
                                             const float* __restrict__ x,
                                             int lane) {
    float acc = 0.f;
#pragma unroll
    for (int k = 0; k < 16; k++)
        acc += W[lane + 32 * k] * x[lane + 32 * k];
#pragma unroll
    for (int o = 16; o; o >>= 1)
        acc += __shfl_xor_sync(0xffffffffu, acc, o);
    return acc;
}

// lane j of the warp computes (Wrow[0:512] . M[:, j]) where M is [512,32] row-major
__device__ __forceinline__ float row_times_M(const float* __restrict__ Wrow,
                                             const float* __restrict__ M,
                                             int lane) {
    float acc = 0.f;
#pragma unroll 8
    for (int c = 0; c < HID; c++)
        acc += Wrow[c] * M[c * QD + lane];
    return acc;
}

// ---------------- stage 1: h1 = sigma(W1 q + b1), g1 = sigma(Wg1 q + bg1) ---
__global__ void k1(const float* __restrict__ q,
                   const float* __restrict__ W1, const float* __restrict__ b1,
                   const float* __restrict__ Wg1, const float* __restrict__ bg1) {
    int t = blockIdx.x * blockDim.x + threadIdx.x;  // 1024 threads
    if (t < HID) {
        float acc = b1[t];
        const float* w = W1 + t * QD;
#pragma unroll
        for (int k = 0; k < QD; k++) acc += w[k] * q[k];
        d_h1[t] = sigm(acc);
    } else if (t < 2 * HID) {
        int r = t - HID;
        float acc = bg1[r];
        const float* w = Wg1 + r * QD;
#pragma unroll
        for (int k = 0; k < QD; k++) acc += w[k] * q[k];
        d_g1[r] = sigm(acc);
    }
}

// ---------------- stage 2: h2, g2, and A1 = diag(s1) W1 ---------------------
__global__ void k2(const float* __restrict__ W1,
                   const float* __restrict__ W2, const float* __restrict__ b2,
                   const float* __restrict__ Wg2, const float* __restrict__ bg2) {
    int tid = threadIdx.x;
    int lane = tid & 31, warp = tid >> 5;
    int gt = blockIdx.x * blockDim.x + tid;
    if (gt < HID * QD) {                      // elementwise A1 (independent)
        int c = gt >> 5;
        float h = d_h1[c];
        d_A1[gt] = h * (1.f - h) * W1[gt];
    }
    int gw = blockIdx.x * (blockDim.x >> 5) + warp;  // 1024 warp tasks
    if (gw < HID) {
        float acc = warp_dot512(W2 + gw * HID, d_h1, lane);
        if (lane == 0) d_h2[gw] = sigm(acc + b2[gw]);
    } else if (gw < 2 * HID) {
        int r = gw - HID;
        float acc = warp_dot512(Wg2 + r * HID, d_g1, lane);
        if (lane == 0) d_g2[r] = sigm(acc + bg2[r]);
    }
}

// ---------------- stage 3: h3 and M1 = diag(s2) W2 A1 -----------------------
__global__ void k3(const float* __restrict__ W2,
                   const float* __restrict__ W3, const float* __restrict__ b3) {
    int tid = threadIdx.x;
    int lane = tid & 31, warp = tid >> 5;
    int gw = blockIdx.x * (blockDim.x >> 5) + warp;  // 1024 warp tasks
    if (gw < HID) {
        float h2 = d_h2[gw];
        float s2 = h2 * (1.f - h2);
        float acc = row_times_M(W2 + gw * HID, d_A1, lane);
        d_M1[gw * QD + lane] = s2 * acc;
    } else if (gw < 2 * HID) {
        int r = gw - HID;
        float acc = warp_dot512(W3 + r * HID, d_h2, lane);
        if (lane == 0) d_h3[r] = sigm(acc + b3[r]);
    }
}

// ---------------- stage 4: M2, l_off, l_diag, g -----------------------------
__global__ void k4(const float* __restrict__ W3,
                   const float* __restrict__ Wd, const float* __restrict__ bd,
                   const float* __restrict__ Wo, const float* __restrict__ bo,
                   const float* __restrict__ Wg3, const float* __restrict__ bg3) {
    int tid = threadIdx.x;
    int lane = tid & 31, warp = tid >> 5;
    int gw = blockIdx.x * (blockDim.x >> 5) + warp;  // 1072 warp tasks
    if (gw < HID) {
        float h3 = d_h3[gw];
        float s3 = h3 * (1.f - h3);
        float acc = row_times_M(W3 + gw * HID, d_M1, lane);
        d_M2[gw * QD + lane] = s3 * acc;
    } else if (gw < HID + OFFN) {
        int p = gw - HID;
        float acc = warp_dot512(Wo + p * HID, d_h3, lane);
        if (lane == 0) d_loff[p] = acc + bo[p];
    } else if (gw < HID + OFFN + QD) {
        int i = gw - HID - OFFN;
        float acc = warp_dot512(Wd + i * HID, d_h3, lane);
        if (lane == 0) d_ldiag[i] = expf(acc + bd[i]);
    } else if (gw < HID + OFFN + 2 * QD) {
        int i = gw - HID - OFFN - QD;
        float acc = warp_dot512(Wg3 + i * HID, d_g2, lane);
        if (lane == 0) d_gvec[i] = acc + bg3[i];
    }
}

// ---------------- stage 5: M3 = dh4 @ M2 ------------------------------------
__global__ void k5(const float* __restrict__ Wd, const float* __restrict__ Wo) {
    int tid = threadIdx.x;
    int lane = tid & 31, warp = tid >> 5;
    int gw = blockIdx.x * (blockDim.x >> 5) + warp;  // 528 warp tasks
    if (gw < QD) {
        float acc = row_times_M(Wd + gw * HID, d_M2, lane);
        d_M3[gw * QD + lane] = d_ldiag[gw] * acc;
    } else if (gw < QD + OFFN) {
        int p = gw - QD;
        float acc = row_times_M(Wo + p * HID, d_M2, lane);
        d_M3[(QD + p) * QD + lane] = acc;
    }
}

// ---------------- stage 6: assemble L/Dqt/Fjk, final tau --------------------
// Uses comp_5 == comp_3, so tau = c1 + c2 + 0.5*c3 - 0.5*c4 + g.
__global__ void k6(const float* __restrict__ q_t, const float* __restrict__ q_tt,
                   float* __restrict__ out) {
    __shared__ float sL[QD][QD];
    __shared__ float sD[QD][QD];
    __shared__ float sF[QD][QD];
    __shared__ float sv[QD + OFFN];
    __shared__ float sqt[QD], sqtt[QD], sLTqt[QD], su1[QD], su2[QD];
    int tid = threadIdx.x;  // 512 threads

    if (tid < QD) { sqt[tid] = q_t[tid]; sqtt[tid] = q_tt[tid]; }
    __syncthreads();

    // L (diag=ldiag, strict lower=loff in tril(-1) row-major order)
    for (int t = tid; t < QD * QD; t += blockDim.x) {
        int i = t >> 5, j = t & 31;
        float v = 0.f;
        if (i == j) v = d_ldiag[i];
        else if (i > j) v = d_loff[(i * (i - 1)) / 2 + j];
        sL[i][j] = v;
    }
    // v = M3 @ q_t  (528 dots of length 32)
    for (int r = tid; r < QD + OFFN; r += blockDim.x) {
        float acc = 0.f;
#pragma unroll
        for (int k = 0; k < QD; k++) acc += d_M3[r * QD + k] * sqt[k];
        sv[r] = acc;
    }
    // Fjk[j][k] = q_t[j]*M3[j][k] + sum_{i>j} q_t[i]*M3[32+p(i,j)][k]
    for (int t = tid; t < QD * QD; t += blockDim.x) {
        int j = t >> 5, k = t & 31;
        float f = sqt[j] * d_M3[j * QD + k];
        for (int i = j + 1; i < QD; i++)
            f += sqt[i] * d_M3[(QD + (i * (i - 1)) / 2 + j) * QD + k];
        sF[j][k] = f;
    }
    __syncthreads();

    // Dqt = tril-assemble(v)
    for (int t = tid; t < QD * QD; t += blockDim.x) {
        int i = t >> 5, j = t & 31;
        float v = 0.f;
        if (i == j) v = sv[i];
        else if (i > j) v = sv[QD + (i * (i - 1)) / 2 + j];
        sD[i][j] = v;
    }
    // LTqt = L^T q_t ; u1 = L^T q_tt
    if (tid < QD) {
        int j = tid;
        float a = 0.f, b = 0.f;
        for (int i = 0; i < QD; i++) { a += sL[i][j] * sqt[i]; b += sL[i][j] * sqtt[i]; }
        sLTqt[j] = a; su1[j] = b;
    }
    __syncthreads();

    // u2 = Dqt^T q_t
    if (tid < QD) {
        int j = tid;
        float a = 0.f;
        for (int i = 0; i < QD; i++) a += sD[i][j] * sqt[i];
        su2[j] = a;
    }
    __syncthreads();

    if (tid < QD) {
        int i = tid;
        float c1 = 0.f, c2 = 0.f, c3 = 0.f, c4 = 0.f;
        for (int j = 0; j < QD; j++) {
            c1 += sL[i][j] * su1[j];     // L (L^T q_tt)
            c2 += sL[i][j] * su2[j];     // L (Dqt^T q_t)
            c3 += sD[i][j] * sLTqt[j];   // Dqt LTqt   (== comp_5)
            c4 += sF[i][j] * sLTqt[j];   // Fjk LTqt
        }
        out[i] = c1 + c2 + 0.5f * c3 - 0.5f * c4 + d_gvec[i];
    }
}

// ---------------- launch ----------------------------------------------------
extern "C" void kernel_launch(void* const* d_in, const int* in_sizes, int n_in,
                              void* d_out, int out_size) {
    const float* q    = (const float*)d_in[0];
    const float* q_t  = (const float*)d_in[1];
    const float* q_tt = (const float*)d_in[2];
    const float* W1   = (const float*)d_in[3];
    const float* b1   = (const float*)d_in[4];
    const float* W2   = (const float*)d_in[5];
    const float* b2   = (const float*)d_in[6];
    const float* W3   = (const float*)d_in[7];
    const float* b3   = (const float*)d_in[8];
    const float* Wd   = (const float*)d_in[9];
    const float* bd   = (const float*)d_in[10];
    const float* Wo   = (const float*)d_in[11];
    const float* bo   = (const float*)d_in[12];
    const float* Wg1  = (const float*)d_in[13];
    const float* bg1  = (const float*)d_in[14];
    const float* Wg2  = (const float*)d_in[15];
    const float* bg2  = (const float*)d_in[16];
    const float* Wg3  = (const float*)d_in[17];
    const float* bg3  = (const float*)d_in[18];
    float* out = (float*)d_out;

    k1<<<8, 128>>>(q, W1, b1, Wg1, bg1);
    k2<<<128, 256>>>(W1, W2, b2, Wg2, bg2);
    k3<<<128, 256>>>(W2, W3, b3);
    k4<<<134, 256>>>(W3, Wd, bd, Wo, bo, Wg3, bg3);
    k5<<<66, 256>>>(Wd, Wo);
    k6<<<1, 512>>>(q_t, q_tt, out);
}

// round 2
// speedup vs baseline: 2.3087x; 2.3087x over previous
#include <cuda_runtime.h>
#include <math.h>

#define HID 512
#define QD 32
#define OFFN 496

// ---------------- scratch (device globals) ----------------------------------
__device__ float d_h1[HID], d_g1[HID], d_h2[HID], d_g2[HID], d_h3[HID];
__device__ float d_A1[HID * QD];     // diag(s1) W1                [512,32]
__device__ float d_M1[HID * QD];     // diag(s2) W2 A1             [512,32]
__device__ float d_M2[HID * QD];     // diag(s3) W3 M1             [512,32]
__device__ float d_Bo[QD * HID];     // Bo[j,c] = sum_{i>j} qt[i] Wo[p(i,j),c]
__device__ float d_wvec[HID];        // w = M2 @ q_t               [512]
__device__ float d_v[QD + OFFN];     // v = dh4 @ w                [528]
__device__ float d_F[QD * QD];       // F = Beff @ M2              [32,32]
__device__ float d_ldiag[QD], d_loff[OFFN], d_gvec[QD];

__device__ __forceinline__ float sigm(float x) { return 1.f / (1.f + expf(-x)); }

// float4 warp dot of length 512; result valid in all lanes
__device__ __forceinline__ float wdot512(const float* __restrict__ W,
                                         const float* __restrict__ x, int lane) {
    const float4* W4 = (const float4*)W;
    const float4* x4 = (const float4*)x;
    float a0 = 0.f, a1 = 0.f, a2 = 0.f, a3 = 0.f;
    float4 wa = __ldg(W4 + lane);      float4 xa = __ldg(x4 + lane);
    float4 wb = __ldg(W4 + lane + 32); float4 xb = __ldg(x4 + lane + 32);
    float4 wc = __ldg(W4 + lane + 64); float4 xc = __ldg(x4 + lane + 64);
    float4 wd = __ldg(W4 + lane + 96); float4 xd = __ldg(x4 + lane + 96);
    a0 = wa.x * xa.x + wa.y * xa.y + wa.z * xa.z + wa.w * xa.w;
    a1 = wb.x * xb.x + wb.y * xb.y + wb.z * xb.z + wb.w * xb.w;
    a2 = wc.x * xc.x + wc.y * xc.y + wc.z * xc.z + wc.w * xc.w;
    a3 = wd.x * xd.x + wd.y * xd.y + wd.z * xd.z + wd.w * xd.w;
    float acc = (a0 + a1) + (a2 + a3);
#pragma unroll
    for (int o = 16; o; o >>= 1) acc += __shfl_xor_sync(0xffffffffu, acc, o);
    return acc;
}

// ---------------- k1: Bo, h1, g1 --------------------------------------------
__global__ void k1(const float* __restrict__ q, const float* __restrict__ q_t,
                   const float* __restrict__ W1, const float* __restrict__ b1,
                   const float* __restrict__ Wg1, const float* __restrict__ bg1,
                   const float* __restrict__ Wo) {
    __shared__ float sqt[QD];
    int tid = threadIdx.x;
    if (tid < QD) sqt[tid] = q_t[tid];
    __syncthreads();
    int t = blockIdx.x * blockDim.x + tid;
    if (t < QD * HID) {                                  // Bo
        int a = t >> 9, c = t & 511;
        float acc = 0.f;
        for (int i = a + 1; i < QD; i++)
            acc += sqt[i] * __ldg(Wo + (((i * (i - 1)) >> 1) + a) * HID + c);
        d_Bo[t] = acc;
    } else if (t < QD * HID + HID) {                     // h1
        int r = t - QD * HID;
        float acc = b1[r];
        const float4* w4 = (const float4*)(W1 + r * QD);
        const float4* q4 = (const float4*)q;
#pragma unroll
        for (int k = 0; k < 8; k++) {
            float4 a = __ldg(w4 + k), b = __ldg(q4 + k);
            acc += a.x * b.x + a.y * b.y + a.z * b.z + a.w * b.w;
        }
        d_h1[r] = sigm(acc);
    } else if (t < QD * HID + 2 * HID) {                 // g1
        int r = t - QD * HID - HID;
        float acc = bg1[r];
        const float4* w4 = (const float4*)(Wg1 + r * QD);
        const float4* q4 = (const float4*)q;
#pragma unroll
        for (int k = 0; k < 8; k++) {
            float4 a = __ldg(w4 + k), b = __ldg(q4 + k);
            acc += a.x * b.x + a.y * b.y + a.z * b.z + a.w * b.w;
        }
        d_g1[r] = sigm(acc);
    }
}

// ---------------- k2: A1, h2, g2 --------------------------------------------
__global__ void k2(const float* __restrict__ W1,
                   const float* __restrict__ W2, const float* __restrict__ b2,
                   const float* __restrict__ Wg2, const float* __restrict__ bg2) {
    int tid = threadIdx.x;
    int lane = tid & 31, warp = tid >> 5;
    int t = blockIdx.x * blockDim.x + tid;
    if (t < HID * QD / 4) {                              // A1 as float4
        float4 wv = __ldg(((const float4*)W1) + t);
        float h = d_h1[t >> 3];
        float s = h * (1.f - h);
        ((float4*)d_A1)[t] = make_float4(s * wv.x, s * wv.y, s * wv.z, s * wv.w);
    }
    int gw = blockIdx.x * 8 + warp;
    if (gw < HID) {
        float acc = wdot512(W2 + gw * HID, d_h1, lane);
        if (lane == 0) d_h2[gw] = sigm(acc + b2[gw]);
    } else if (gw < 2 * HID) {
        int r = gw - HID;
        float acc = wdot512(Wg2 + r * HID, d_g1, lane);
        if (lane == 0) d_g2[r] = sigm(acc + bg2[r]);
    }
}

// GEMM core: block computes 4 rows of Y = diag(s(h)) * (W @ M), M [512,32].
// Warp w covers c in [64w, 64w+64). Returns per-thread value in combine phase.
__device__ __forceinline__ void gemm4(const float* __restrict__ W, int rbase,
                                      const float* __restrict__ M,
                                      const float* __restrict__ hvec,
                                      float* __restrict__ Y,
                                      const float* __restrict__ qt_for_w,
                                      float* __restrict__ wvec_out) {
    __shared__ float sp[8][4][33];
    int tid = threadIdx.x;
    int lane = tid & 31, w = tid >> 5;
    const float4* W0 = (const float4*)(W + (rbase + 0) * HID);
    const float4* W1p = (const float4*)(W + (rbase + 1) * HID);
    const float4* W2p = (const float4*)(W + (rbase + 2) * HID);
    const float4* W3p = (const float4*)(W + (rbase + 3) * HID);
    float a0 = 0.f, a1 = 0.f, a2 = 0.f, a3 = 0.f;
    int base = w * 16;
#pragma unroll
    for (int t = 0; t < 16; t++) {
        int c4 = base + t;
        float4 v0 = __ldg(W0 + c4);
        float4 v1 = __ldg(W1p + c4);
        float4 v2 = __ldg(W2p + c4);
        float4 v3 = __ldg(W3p + c4);
        int c = c4 * 4;
        float m0 = __ldg(M + (c + 0) * QD + lane);
        float m1 = __ldg(M + (c + 1) * QD + lane);
        float m2 = __ldg(M + (c + 2) * QD + lane);
        float m3 = __ldg(M + (c + 3) * QD + lane);
        a0 += v0.x * m0 + v0.y * m1 + v0.z * m2 + v0.w * m3;
        a1 += v1.x * m0 + v1.y * m1 + v1.z * m2 + v1.w * m3;
        a2 += v2.x * m0 + v2.y * m1 + v2.z * m2 + v2.w * m3;
        a3 += v3.x * m0 + v3.y * m1 + v3.z * m2 + v3.w * m3;
    }
    sp[w][0][lane] = a0; sp[w][1][lane] = a1;
    sp[w][2][lane] = a2; sp[w][3][lane] = a3;
    __syncthreads();
    if (tid < 128) {
        int i = tid >> 5, j = tid & 31;
        float s = 0.f;
#pragma unroll
        for (int u = 0; u < 8; u++) s += sp[u][i][j];
        int r = rbase + i;
        float h = d_h2[0];  // placeholder avoided; use hvec
        h = hvec[r];
        float val = h * (1.f - h) * s;
        Y[r * QD + j] = val;
        if (wvec_out) {
            float contrib = val * __ldg(qt_for_w + j);
#pragma unroll
            for (int o = 16; o; o >>= 1)
                contrib += __shfl_xor_sync(0xffffffffu, contrib, o);
            if (j == 0) wvec_out[r] = contrib;
        }
    }
}

// ---------------- k3: M1 GEMM + h3 ------------------------------------------
__global__ void k3(const float* __restrict__ W2,
                   const float* __restrict__ W3, const float* __restrict__ b3) {
    int b = blockIdx.x;
    if (b < 128) {
        gemm4(W2, b * 4, d_A1, d_h2, d_M1, nullptr, nullptr);
    } else {
        int tid = threadIdx.x;
        int lane = tid & 31, warp = tid >> 5;
        int r = (b - 128) * 8 + warp;  // 0..511
        float acc = wdot512(W3 + r * HID, d_h2, lane);
        if (lane == 0) d_h3[r] = sigm(acc + b3[r]);
    }
}

// ---------------- k4: M2 GEMM (+w) + loff/ldiag/gvec -------------------------
__global__ void k4(const float* __restrict__ W3, const float* __restrict__ q_t,
                   const float* __restrict__ Wd, const float* __restrict__ bd,
                   const float* __restrict__ Wo, const float* __restrict__ bo,
                   const float* __restrict__ Wg3, const float* __restrict__ bg3) {
    int b = blockIdx.x;
    if (b < 128) {
        gemm4(W3, b * 4, d_M1, d_h3, d_M2, q_t, d_wvec);
    } else {
        int tid = threadIdx.x;
        int lane = tid & 31, warp = tid >> 5;
        int gw = (b - 128) * 8 + warp;  // 0..559
        if (gw < OFFN) {
            float acc = wdot512(Wo + gw * HID, d_h3, lane);
            if (lane == 0) d_loff[gw] = acc + bo[gw];
        } else if (gw < OFFN + QD) {
            int i = gw - OFFN;
            float acc = wdot512(Wd + i * HID, d_h3, lane);
            if (lane == 0) d_ldiag[i] = expf(acc + bd[i]);
        } else if (gw < OFFN + 2 * QD) {
            int i = gw - OFFN - QD;
            float acc = wdot512(Wg3 + i * HID, d_g2, lane);
            if (lane == 0) d_gvec[i] = acc + bg3[i];
        }
    }
}

// ---------------- k5: F = Beff @ M2  and  v = dh4 @ w ------------------------
__global__ void k5(const float* __restrict__ q_t,
                   const float* __restrict__ Wd, const float* __restrict__ Wo) {
    int b = blockIdx.x;
    int tid = threadIdx.x;
    int lane = tid & 31, w = tid >> 5;
    if (b < 8) {
        // F rows rbase..rbase+3 ; Beff[j,c] = qt[j]*ldiag[j]*Wd[j,c] + Bo[j,c]
        __shared__ float sp[8][4][33];
        __shared__ float sqld[4];
        int rbase = b * 4;
        if (tid < 4) sqld[tid] = __ldg(q_t + rbase + tid) * d_ldiag[rbase + tid];
        __syncthreads();
        const float4* Wd0 = (const float4*)(Wd + (rbase + 0) * HID);
        const float4* Wd1 = (const float4*)(Wd + (rbase + 1) * HID);
        const float4* Wd2 = (const float4*)(Wd + (rbase + 2) * HID);
        const float4* Wd3 = (const float4*)(Wd + (rbase + 3) * HID);
        const float4* Bo0 = (const float4*)(d_Bo + (rbase + 0) * HID);
        const float4* Bo1 = (const float4*)(d_Bo + (rbase + 1) * HID);
        const float4* Bo2 = (const float4*)(d_Bo + (rbase + 2) * HID);
        const float4* Bo3 = (const float4*)(d_Bo + (rbase + 3) * HID);
        float q0 = sqld[0], q1 = sqld[1], q2 = sqld[2], q3 = sqld[3];
        float a0 = 0.f, a1 = 0.f, a2 = 0.f, a3 = 0.f;
        int base = w * 16;
#pragma unroll
        for (int t = 0; t < 16; t++) {
            int c4 = base + t;
            float4 wv0 = __ldg(Wd0 + c4), bv0 = __ldg(Bo0 + c4);
            float4 wv1 = __ldg(Wd1 + c4), bv1 = __ldg(Bo1 + c4);
            float4 wv2 = __ldg(Wd2 + c4), bv2 = __ldg(Bo2 + c4);
            float4 wv3 = __ldg(Wd3 + c4), bv3 = __ldg(Bo3 + c4);
            int c = c4 * 4;
            float m0 = __ldg(d_M2 + (c + 0) * QD + lane);
            float m1 = __ldg(d_M2 + (c + 1) * QD + lane);
            float m2 = __ldg(d_M2 + (c + 2) * QD + lane);
            float m3 = __ldg(d_M2 + (c + 3) * QD + lane);
            a0 += (q0 * wv0.x + bv0.x) * m0 + (q0 * wv0.y + bv0.y) * m1 +
                  (q0 * wv0.z + bv0.z) * m2 + (q0 * wv0.w + bv0.w) * m3;
            a1 += (q1 * wv1.x + bv1.x) * m0 + (q1 * wv1.y + bv1.y) * m1 +
                  (q1 * wv1.z + bv1.z) * m2 + (q1 * wv1.w + bv1.w) * m3;
            a2 += (q2 * wv2.x + bv2.x) * m0 + (q2 * wv2.y + bv2.y) * m1 +
                  (q2 * wv2.z + bv2.z) * m2 + (q2 * wv2.w + bv2.w) * m3;
            a3 += (q3 * wv3.x + bv3.x) * m0 + (q3 * wv3.y + bv3.y) * m1 +
                  (q3 * wv3.z + bv3.z) * m2 + (q3 * wv3.w + bv3.w) * m3;
        }
        sp[w][0][lane] = a0; sp[w][1][lane] = a1;
        sp[w][2][lane] = a2; sp[w][3][lane] = a3;
        __syncthreads();
        if (tid < 128) {
            int i = tid >> 5, j = tid & 31;
            float s = 0.f;
#pragma unroll
            for (int u = 0; u < 8; u++) s += sp[u][i][j];
            d_F[(rbase + i) * QD + j] = s;
        }
    } else {
        int r = (b - 8) * 8 + w;  // 0..527
        if (r < QD) {
            float acc = wdot512(Wd + r * HID, d_wvec, lane);
            if (lane == 0) d_v[r] = d_ldiag[r] * acc;
        } else {
            int p = r - QD;
            float acc = wdot512(Wo + p * HID, d_wvec, lane);
            if (lane == 0) d_v[r] = acc;
        }
    }
}

// ---------------- k6: final assembly -----------------------------------------
// tau = c1 + c2 + 0.5*c3 - 0.5*c4 + g   (comp_5 == comp_3)
__global__ void k6(const float* __restrict__ q_t, const float* __restrict__ q_tt,
                   float* __restrict__ out) {
    __shared__ float sL[QD][QD + 1];
    __shared__ float sD[QD][QD + 1];
    __shared__ float sqt[QD], sqtt[QD], sLTqt[QD], su1[QD], su2[QD];
    int tid = threadIdx.x;  // 256
    if (tid < QD) { sqt[tid] = q_t[tid]; sqtt[tid] = q_tt[tid]; }
    __syncthreads();
    for (int t = tid; t < QD * QD; t += 256) {
        int i = t >> 5, j = t & 31;
        float lv = 0.f, dv = 0.f;
        if (i == j) { lv = d_ldiag[i]; dv = d_v[i]; }
        else if (i > j) {
            int p = ((i * (i - 1)) >> 1) + j;
            lv = d_loff[p]; dv = d_v[QD + p];
        }
        sL[i][j] = lv; sD[i][j] = dv;
    }
    __syncthreads();
    if (tid < QD) {
        int j = tid;
        float a = 0.f, b = 0.f, c = 0.f;
#pragma unroll
        for (int i = 0; i < QD; i++) {
            a += sL[i][j] * sqt[i];
            b += sL[i][j] * sqtt[i];
            c += sD[i][j] * sqt[i];
        }
        sLTqt[j] = a; su1[j] = b; su2[j] = c;
    }
    __syncthreads();
    if (tid < QD) {
        int i = tid;
        float acc = d_gvec[i];
#pragma unroll
        for (int j = 0; j < QD; j++) {
            acc += sL[i][j] * (su1[j] + su2[j]) +
                   0.5f * (sD[i][j] - d_F[i * QD + j]) * sLTqt[j];
        }
        out[i] = acc;
    }
}

// ---------------- launch ------------------------------------------------------
extern "C" void kernel_launch(void* const* d_in, const int* in_sizes, int n_in,
                              void* d_out, int out_size) {
    const float* q    = (const float*)d_in[0];
    const float* q_t  = (const float*)d_in[1];
    const float* q_tt = (const float*)d_in[2];
    const float* W1   = (const float*)d_in[3];
    const float* b1   = (const float*)d_in[4];
    const float* W2   = (const float*)d_in[5];
    const float* b2   = (const float*)d_in[6];
    const float* W3   = (const float*)d_in[7];
    const float* b3   = (const float*)d_in[8];
    const float* Wd   = (const float*)d_in[9];
    const float* bd   = (const float*)d_in[10];
    const float* Wo   = (const float*)d_in[11];
    const float* bo   = (const float*)d_in[12];
    const float* Wg1  = (const float*)d_in[13];
    const float* bg1  = (const float*)d_in[14];
    const float* Wg2  = (const float*)d_in[15];
    const float* bg2  = (const float*)d_in[16];
    const float* Wg3  = (const float*)d_in[17];
    const float* bg3  = (const float*)d_in[18];
    float* out = (float*)d_out;

    k1<<<68, 256>>>(q, q_t, W1, b1, Wg1, bg1, Wo);
    k2<<<128, 256>>>(W1, W2, b2, Wg2, bg2);
    k3<<<192, 256>>>(W2, W3, b3);
    k4<<<198, 256>>>(W3, q_t, Wd, bd, Wo, bo, Wg3, bg3);
    k5<<<74, 256>>>(q_t, Wd, Wo);
    k6<<<1, 256>>>(q_t, q_tt, out);
}